// round 8
// baseline (speedup 1.0000x reference)
#include <cuda_runtime.h>

#define NN 100000
#define NE 1250000
#define HID 64
#define NG 256
#define NC 10
#define TR 128           // rows per GEMM/fused block
#define GEMM_T 256       // threads per GEMM/fused block
#define NBLK 391         // ceil(NN/256)
#define GEMM_SMEM_BYTES (TR * 68 * 4 + 64 * 64 * 4)   // sIn + sW = 51200

typedef unsigned long long ull;

// ---------------- scratch (static device globals; no allocation) ----------------
__device__ int   g_cnt_in[NN];        // in-degree (excluding self loop)
__device__ int   g_fill[NN];          // CSR fill cursors
__device__ int   g_rowstart[NN + 1];  // CSR row offsets
__device__ float g_dinv[NN];          // 1/sqrt(deg+1)
__device__ int   g_bsum[NBLK];        // per-block degree sums
__device__ int2  g_csr[NE];           // (src, bitcast(norm)) per edge, grouped by dst
__device__ float g_buf0[NN * HID];    // layer buffers (ping-pong)
__device__ float g_buf1[NN * HID];
__device__ float g_buf2[NN * HID];
__device__ float g_pool[NG * HID];    // per-graph feature sums
__device__ float g_gcnt[NG];          // per-graph node counts
__device__ int   g_is64;              // 1 if index arrays are int64, 0 if int32

__device__ __forceinline__ float* buf_sel(int which) {
    return (which == 0) ? g_buf0 : (which == 1) ? g_buf1 : g_buf2;
}
__device__ __forceinline__ const float* cbuf_sel(int which) {
    return (which == 0) ? g_buf0 : (which == 1) ? g_buf1 : g_buf2;
}

__device__ __forceinline__ int ld_idx(const void* p, long long e) {
    if (g_is64) return (int)((const long long*)p)[e];
    return ((const int*)p)[e];
}

// packed f32x2 helpers (FFMA2 — ptxas never emits this from C++)
__device__ __forceinline__ ull ffma2(ull a, ull b, ull c) {
    ull d;
    asm("fma.rn.f32x2 %0, %1, %2, %3;" : "=l"(d) : "l"(a), "l"(b), "l"(c));
    return d;
}
__device__ __forceinline__ ull bcast2(float x) {
    ull d;
    asm("mov.b64 %0, {%1, %1};" : "=l"(d) : "f"(x));
    return d;
}

// ---------------- CSR gather for one destination row, 16 threads/row ----------------
// Returns this lane's float4 chunk (cols c..c+3) of:
//   dinv[i]^2 * in[i] + sum_e w_e * in[src_e]
__device__ __forceinline__ float4 gather_row(const float* __restrict__ in, int i, int c)
{
    int beg = g_rowstart[i];
    int end = g_rowstart[i + 1];
    float di = g_dinv[i];
    float sw = di * di;

    float4 v = *(const float4*)&in[i * 64 + c];
    float4 s0 = make_float4(v.x * sw, v.y * sw, v.z * sw, v.w * sw);
    float4 s1 = make_float4(0.f, 0.f, 0.f, 0.f);

    int e = beg;
    for (; e + 3 < end; e += 4) {
        int2 p0 = g_csr[e];
        int2 p1 = g_csr[e + 1];
        int2 p2 = g_csr[e + 2];
        int2 p3 = g_csr[e + 3];
        float w0 = __int_as_float(p0.y), w1 = __int_as_float(p1.y);
        float w2 = __int_as_float(p2.y), w3 = __int_as_float(p3.y);
        float4 v0 = *(const float4*)&in[p0.x * 64 + c];
        float4 v1 = *(const float4*)&in[p1.x * 64 + c];
        float4 v2 = *(const float4*)&in[p2.x * 64 + c];
        float4 v3 = *(const float4*)&in[p3.x * 64 + c];
        s0.x += v0.x * w0 + v1.x * w1;  s1.x += v2.x * w2 + v3.x * w3;
        s0.y += v0.y * w0 + v1.y * w1;  s1.y += v2.y * w2 + v3.y * w3;
        s0.z += v0.z * w0 + v1.z * w1;  s1.z += v2.z * w2 + v3.z * w3;
        s0.w += v0.w * w0 + v1.w * w1;  s1.w += v2.w * w2 + v3.w * w3;
    }
    for (; e < end; e++) {
        int2 p0 = g_csr[e];
        float w0 = __int_as_float(p0.y);
        float4 v0 = *(const float4*)&in[p0.x * 64 + c];
        s0.x += v0.x * w0; s0.y += v0.y * w0; s0.z += v0.z * w0; s0.w += v0.w * w0;
    }
    return make_float4(s0.x + s1.x, s0.y + s1.y, s0.z + s1.z, s0.w + s1.w);
}

// ---------------- preprocessing ----------------
// init + dtype detect in one kernel
__global__ void init_kernel(const int* __restrict__ ei32) {
    int i = blockIdx.x * blockDim.x + threadIdx.x;
    if (i < NN) g_cnt_in[i] = 0;
    if (i == 0) {
        int allzero = 1;
        for (int j = 1; j < 128; j += 2)
            if (ei32[j] != 0) { allzero = 0; break; }
        g_is64 = allzero;
    }
}

__global__ void count_kernel(const void* __restrict__ ei) {
    int e = blockIdx.x * blockDim.x + threadIdx.x;
    if (e >= NE) return;
    atomicAdd(&g_cnt_in[ld_idx(ei, (long long)NE + e)], 1);
}

// per-block degree sums (+dinv fused)
__global__ void blocksum_kernel() {
    __shared__ int sred[256];
    int i = blockIdx.x * 256 + threadIdx.x;
    int v = (i < NN) ? g_cnt_in[i] : 0;
    if (i < NN) g_dinv[i] = rsqrtf((float)v + 1.0f);
    sred[threadIdx.x] = v;
    __syncthreads();
    for (int h = 128; h > 0; h >>= 1) {
        if (threadIdx.x < h) sred[threadIdx.x] += sred[threadIdx.x + h];
        __syncthreads();
    }
    if (threadIdx.x == 0) g_bsum[blockIdx.x] = sred[0];
}

// rowstart: block prefix over g_bsum (inline) + per-block scan (+fill zero fused)
__global__ void rowstart_kernel() {
    __shared__ int s[256];
    int t = threadIdx.x;

    // prefix of preceding block sums
    int pre = 0;
    for (int j = t; j < blockIdx.x; j += 256) pre += g_bsum[j];
    s[t] = pre;
    __syncthreads();
    for (int h = 128; h > 0; h >>= 1) {
        if (t < h) s[t] += s[t + h];
        __syncthreads();
    }
    int base = s[0];
    __syncthreads();

    // block-local inclusive scan of counts
    int i = blockIdx.x * 256 + t;
    int own = (i < NN) ? g_cnt_in[i] : 0;
    s[t] = own;
    __syncthreads();
    for (int off = 1; off < 256; off <<= 1) {
        int v = (t >= off) ? s[t - off] : 0;
        __syncthreads();
        s[t] += v;
        __syncthreads();
    }
    if (i < NN) {
        g_rowstart[i] = base + s[t] - own;
        g_fill[i] = 0;
    }
    if (i == 0) g_rowstart[NN] = NE;
}

__global__ void fill_kernel(const void* __restrict__ ei) {
    int e = blockIdx.x * blockDim.x + threadIdx.x;
    if (e >= NE) return;
    int s = ld_idx(ei, e);
    int d = ld_idx(ei, (long long)NE + e);
    int pos = g_rowstart[d] + atomicAdd(&g_fill[d], 1);
    float w = g_dinv[s] * g_dinv[d];
    g_csr[pos] = make_int2(s, __float_as_int(w));
}

// ---------------- GEMM core (FFMA2, 128x64 tile, operand already in sIn/sW) -------
__device__ __forceinline__ void gemm_core(const float* sIn, const float* sW,
                                          float* out, int r0, int tid)
{
    const int cx = tid & 7;            // col group (8 cols)
    const int ry4 = (tid >> 3) * 4;    // first of 4 rows

    ull acc[4][4] = {};

    #pragma unroll 4
    for (int k = 0; k < 64; k++) {
        const ulonglong2* wp = (const ulonglong2*)&sW[k * 64 + cx * 8];
        ulonglong2 wa = wp[0];
        ulonglong2 wb = wp[1];
        #pragma unroll
        for (int i = 0; i < 4; i++) {
            ull a2 = bcast2(sIn[(ry4 + i) * 68 + k]);
            acc[i][0] = ffma2(a2, wa.x, acc[i][0]);
            acc[i][1] = ffma2(a2, wa.y, acc[i][1]);
            acc[i][2] = ffma2(a2, wb.x, acc[i][2]);
            acc[i][3] = ffma2(a2, wb.y, acc[i][3]);
        }
    }

    #pragma unroll
    for (int i = 0; i < 4; i++) {
        int gr = r0 + ry4 + i;
        if (gr < NN) {
            union { ull u[4]; float4 f[2]; } row;
            row.u[0] = acc[i][0]; row.u[1] = acc[i][1];
            row.u[2] = acc[i][2]; row.u[3] = acc[i][3];
            *(float4*)&out[gr * 64 + cx * 8]     = row.f[0];
            *(float4*)&out[gr * 64 + cx * 8 + 4] = row.f[1];
        }
    }
}

// ---------------- layer 1 GEMM: buf0 = x @ W1 ----------------
__global__ void __launch_bounds__(GEMM_T) gemm_kernel(
    const float* __restrict__ in, const float* __restrict__ W)
{
    extern __shared__ float smem[];
    float* sIn = smem;                 // [r][k], stride 68
    float* sW  = smem + TR * 68;       // [k][j]

    int tid = threadIdx.x;
    int r0 = blockIdx.x * TR;

    for (int q = tid; q < 64 * 16; q += GEMM_T) {
        int kk = q >> 4, j4 = q & 15;
        *(float4*)&sW[kk * 64 + j4 * 4] = *(const float4*)&W[kk * 64 + j4 * 4];
    }
    for (int q = tid; q < TR * 16; q += GEMM_T) {
        int r = q >> 4, k4 = q & 15;
        int gr = r0 + r;
        float4 v = make_float4(0.f, 0.f, 0.f, 0.f);
        if (gr < NN) v = *(const float4*)&in[gr * 64 + k4 * 4];
        *(float4*)&sIn[r * 68 + k4 * 4] = v;
    }
    __syncthreads();

    gemm_core(sIn, sW, g_buf0, r0, tid);
}

// ---------------- fused layer: out = relu(gather(in) + b) @ W ----------------
// Gather straight into smem tile, then GEMM. No intermediate global buffer.
__global__ void __launch_bounds__(GEMM_T) fused_layer_kernel(
    int in_sel, const float* __restrict__ bias,
    const float* __restrict__ W, int out_sel)
{
    extern __shared__ float smem[];
    float* sIn = smem;
    float* sW  = smem + TR * 68;

    const float* in = cbuf_sel(in_sel);
    float* out = buf_sel(out_sel);

    int tid = threadIdx.x;
    int r0 = blockIdx.x * TR;

    // W loads first (independent of gather)
    for (int q = tid; q < 64 * 16; q += GEMM_T) {
        int kk = q >> 4, j4 = q & 15;
        *(float4*)&sW[kk * 64 + j4 * 4] = *(const float4*)&W[kk * 64 + j4 * 4];
    }

    // gather phase: 16 threads per row, 16 rows per pass, 8 passes
    int rsub = tid >> 4;               // 0..15
    int c = (tid & 15) << 2;           // col offset 0..60
    float4 bv = *(const float4*)&bias[c];

    #pragma unroll
    for (int pass = 0; pass < TR / 16; pass++) {
        int r = pass * 16 + rsub;
        int gr = r0 + r;
        float4 s = make_float4(0.f, 0.f, 0.f, 0.f);
        if (gr < NN) {
            s = gather_row(in, gr, c);
            s.x = fmaxf(s.x + bv.x, 0.f);
            s.y = fmaxf(s.y + bv.y, 0.f);
            s.z = fmaxf(s.z + bv.z, 0.f);
            s.w = fmaxf(s.w + bv.w, 0.f);
        }
        *(float4*)&sIn[r * 68 + c] = s;
    }
    __syncthreads();

    gemm_core(sIn, sW, out, r0, tid);
}

// ---------------- final gather (layer 3 aggregation, no activation) ----------------
__global__ void __launch_bounds__(256) gather_kernel(int in_sel, int out_sel)
{
    const float* in = cbuf_sel(in_sel);
    float* acc_out = buf_sel(out_sel);

    int t = blockIdx.x * blockDim.x + threadIdx.x;
    int i = t >> 4;
    if (i >= NN) return;
    int c = (t & 15) << 2;

    float4 s = gather_row(in, i, c);
    *(float4*)&acc_out[i * 64 + c] = s;
}

// ---------------- segmented mean pool (batch is sorted; no atomics) ----------------
__global__ void __launch_bounds__(256) pool_kernel(int in_sel, const void* __restrict__ batch)
{
    __shared__ float4 sP[16][16];
    const float* acc = cbuf_sel(in_sel);
    int g = blockIdx.x;
    int tid = threadIdx.x;
    int chunk = tid >> 4;
    int c4 = tid & 15;

    int lo = 0, hi = NN;
    while (lo < hi) { int mid = (lo + hi) >> 1; if (ld_idx(batch, mid) < g) lo = mid + 1; else hi = mid; }
    int start = lo;
    lo = start; hi = NN;
    while (lo < hi) { int mid = (lo + hi) >> 1; if (ld_idx(batch, mid) < g + 1) lo = mid + 1; else hi = mid; }
    int end = lo;

    float4 sum = make_float4(0.f, 0.f, 0.f, 0.f);
    for (int n = start + chunk; n < end; n += 16) {
        float4 v = *(const float4*)&acc[n * 64 + c4 * 4];
        sum.x += v.x; sum.y += v.y; sum.z += v.z; sum.w += v.w;
    }
    sP[chunk][c4] = sum;
    __syncthreads();
    for (int h = 8; h > 0; h >>= 1) {
        if (chunk < h) {
            float4 a = sP[chunk][c4], b = sP[chunk + h][c4];
            sP[chunk][c4] = make_float4(a.x + b.x, a.y + b.y, a.z + b.z, a.w + b.w);
        }
        __syncthreads();
    }
    if (chunk == 0) *(float4*)&g_pool[g * 64 + c4 * 4] = sP[0][c4];
    if (tid == 0) g_gcnt[g] = (float)(end - start);
}

// ---------------- final: out[g][c] = (pool[g]/cnt + b3) @ Wlin + blin ----------------
__global__ void final_kernel(const float* __restrict__ b3,
                             const float* __restrict__ Wlin,
                             const float* __restrict__ blin,
                             float* __restrict__ out)
{
    int idx = blockIdx.x * blockDim.x + threadIdx.x;
    if (idx >= NG * NC) return;
    int g = idx / NC, c = idx % NC;
    float inv = 1.0f / fmaxf(g_gcnt[g], 1.0f);
    float sum = blin[c];
    #pragma unroll
    for (int h = 0; h < 64; h++) {
        float v = g_pool[g * 64 + h] * inv + b3[h];
        sum = fmaf(v, Wlin[h * NC + c], sum);
    }
    out[idx] = sum;
}

// ---------------- launch ----------------
extern "C" void kernel_launch(void* const* d_in, const int* in_sizes, int n_in,
                              void* d_out, int out_size)
{
    const float* x     = (const float*)d_in[0];
    const void*  ei    = d_in[1];
    const void*  batch = d_in[2];
    const float* W1 = (const float*)d_in[3];
    const float* b1 = (const float*)d_in[4];
    const float* W2 = (const float*)d_in[5];
    const float* b2 = (const float*)d_in[6];
    const float* W3 = (const float*)d_in[7];
    const float* b3 = (const float*)d_in[8];
    const float* Wlin = (const float*)d_in[9];
    const float* blin = (const float*)d_in[10];
    float* out = (float*)d_out;

    // One-time: raise dynamic smem limit (persistent per-function attribute).
    static bool attr_done = false;
    if (!attr_done) {
        cudaFuncSetAttribute(gemm_kernel,
                             cudaFuncAttributeMaxDynamicSharedMemorySize, GEMM_SMEM_BYTES);
        cudaFuncSetAttribute(fused_layer_kernel,
                             cudaFuncAttributeMaxDynamicSharedMemorySize, GEMM_SMEM_BYTES);
        attr_done = true;
    }

    const int eB = (NE + 255) / 256;
    const int gemmB = (NN + TR - 1) / TR;
    const int gatB = (NN * 16 + 255) / 256;

    // CSR build: init+detect(0) -> count(1) -> blocksum(2) -> rowstart(3) -> fill(4)
    init_kernel<<<NBLK, 256>>>((const int*)ei);
    count_kernel<<<eB, 256>>>(ei);
    blocksum_kernel<<<NBLK, 256>>>();
    rowstart_kernel<<<NBLK, 256>>>();
    fill_kernel<<<eB, 256>>>(ei);

    // layer 1: buf0 = x @ W1                         (launch 5 — ncu capture target)
    gemm_kernel<<<gemmB, GEMM_T, GEMM_SMEM_BYTES>>>(x, W1);
    // layer 2: buf1 = relu(gather(buf0)+b1) @ W2     (fused)
    fused_layer_kernel<<<gemmB, GEMM_T, GEMM_SMEM_BYTES>>>(0, b1, W2, 1);
    // layer 3: buf0 = relu(gather(buf1)+b2) @ W3     (fused)
    fused_layer_kernel<<<gemmB, GEMM_T, GEMM_SMEM_BYTES>>>(1, b2, W3, 0);
    // final aggregation: buf2 = A_hat buf0
    gather_kernel<<<gatB, 256>>>(0, 2);

    // segmented mean pool + classifier (b3 folded into final)
    pool_kernel<<<NG, 256>>>(2, batch);
    final_kernel<<<(NG * NC + 255) / 256, 256>>>(b3, Wlin, blin, out);
}